// round 16
// baseline (speedup 1.0000x reference)
#include <cuda_runtime.h>
#include <cuda_bf16.h>
#include <cstdint>

#define BB 2
#define GG 2048
#define HH 4
#define EE 128

#define TQ 64      // q rows per block (16 warps)
#define TP 64      // p columns per tile
#define PSPLIT 2
#define PRANGE (GG / PSPLIT)      // 1024
#define NTILE (PRANGE / TP)       // 16
#define NT 512     // 16 warps

// ---------------- device scratch ----------------
__device__ float g_Q[BB * GG * 128];     // tf32-rounded
__device__ float g_K[BB * GG * 128];     // tf32-rounded
__device__ float g_V[BB * GG * 128];     // tf32-rounded, natural layout
__device__ float g_pacc[PSPLIT][BB * GG * 128];
__device__ float g_pm[PSPLIT][BB * GG * 4];
__device__ float g_pl[PSPLIT][BB * GG * 4];

// ---------------- helpers ----------------
__device__ __forceinline__ unsigned long long pack2(float a, float b) {
    unsigned long long r;
    asm("mov.b64 %0, {%1, %2};" : "=l"(r) : "f"(a), "f"(b));
    return r;
}
__device__ __forceinline__ void unpack2(unsigned long long v, float& a, float& b) {
    asm("mov.b64 {%0, %1}, %2;" : "=f"(a), "=f"(b) : "l"(v));
}
__device__ __forceinline__ void fma2(unsigned long long& d,
                                     unsigned long long a, unsigned long long b) {
    asm("fma.rn.f32x2 %0, %1, %2, %0;" : "+l"(d) : "l"(a), "l"(b));
}
__device__ __forceinline__ uint32_t to_tf32(float f) {
    uint32_t r;
    asm("cvt.rna.tf32.f32 %0, %1;" : "=r"(r) : "f"(f));
    return r;
}
__device__ __forceinline__ void mma_tf32(float& d0, float& d1, float& d2, float& d3,
                                         uint32_t a0, uint32_t a1, uint32_t a2, uint32_t a3,
                                         uint32_t b0, uint32_t b1) {
    asm volatile("mma.sync.aligned.m16n8k8.row.col.f32.tf32.tf32.f32 "
                 "{%0,%1,%2,%3}, {%4,%5,%6,%7}, {%8,%9}, {%0,%1,%2,%3};"
                 : "+f"(d0), "+f"(d1), "+f"(d2), "+f"(d3)
                 : "r"(a0), "r"(a1), "r"(a2), "r"(a3), "r"(b0), "r"(b1));
}

#define CP_ASYNC16(dst, src) \
    asm volatile("cp.async.cg.shared.global [%0], [%1], 16;" :: "r"(dst), "l"(src))
#define CP_COMMIT() asm volatile("cp.async.commit_group;" ::: "memory")
#define CP_WAIT0()  asm volatile("cp.async.wait_group 0;" ::: "memory")

// =============================================================================
// K0: fused QKV projection; outputs tf32-rounded; V natural layout.
// =============================================================================
__global__ __launch_bounds__(256)
void qkv_kernel(const float* __restrict__ hin,
                const float* __restrict__ Wq,
                const float* __restrict__ Wk,
                const float* __restrict__ Wv)
{
    __shared__ float hs[8 * 128];
    const int tid  = threadIdx.x;
    const int row0 = blockIdx.x * 8;

    for (int i = tid; i < 8 * 128; i += 256)
        hs[i] = hin[(size_t)row0 * 128 + i];
    __syncthreads();

    const int sub   = tid >> 7;
    const int col   = tid & 127;
    const int rbase = sub * 4;

    float aq[4], ak[4], av[4];
#pragma unroll
    for (int r = 0; r < 4; r++) { aq[r] = 0.f; ak[r] = 0.f; av[r] = 0.f; }

    const int hh = col >> 5, k = col & 31;
    const float* wqp = Wq + hh * 128 * 32 + k;
    const float* wkp = Wk + hh * 128 * 32 + k;
    const float* wvp = Wv + hh * 128 * 32 + k;

    for (int d = 0; d < 128; d += 4) {
        float wq[4], wk4[4], wv[4];
#pragma unroll
        for (int u = 0; u < 4; u++) {
            wq[u]  = __ldg(wqp + (d + u) * 32);
            wk4[u] = __ldg(wkp + (d + u) * 32);
            wv[u]  = __ldg(wvp + (d + u) * 32);
        }
#pragma unroll
        for (int u = 0; u < 4; u++) {
#pragma unroll
            for (int r = 0; r < 4; r++) {
                const float hv = hs[(rbase + r) * 128 + d + u];
                aq[r] += hv * wq[u];
                ak[r] += hv * wk4[u];
                av[r] += hv * wv[u];
            }
        }
    }

    const int growbase = row0 + rbase;
#pragma unroll
    for (int r = 0; r < 4; r++) {
        const size_t o = (size_t)(growbase + r) * 128 + col;
        g_Q[o] = __uint_as_float(to_tf32(aq[r]));
        g_K[o] = __uint_as_float(to_tf32(ak[r]));
        g_V[o] = __uint_as_float(to_tf32(av[r]));
    }
}

// =============================================================================
// K1: tf32 warp-MMA scores + AV, SIMT MLP/softmax between, 3-phase per tile.
// grid = (32, 2, 2) = 128 blocks, 512 thr = 16 warps, smem 204,640 B.
// Phase S/A: warp = (head = warp&3, q16 = (warp>>2)*16). Phase M: warp = 4 q.
// =============================================================================
#define SM_K  0                    /* 2 x 64 x 132 = 16896 */
#define SM_V  16896                /* 2 x 64 x 132 = 16896 */
#define SM_SS 33792                /* 4h x 64q x 66 = 16896 (S, then P) */
#define SM_CS 50688                /* 64q x 4h = 256 */
#define SM_WT 50944                /* 108 ull = 216 */
#define SMEM_FLOATS 51160
#define SMEM_BYTES (SMEM_FLOATS * 4)
#define KVBUF 8448                 /* floats per buffer */

__device__ __forceinline__ void stage_cp(uint32_t smaddr, int buf, int b,
                                         int pg0, int tid)
{
    // K and V tiles: 64 rows x 128 floats each (2048 16B chunks each)
#pragma unroll
    for (int j = 0; j < 4; j++) {
        const int c  = tid + j * 512;
        const int r  = c >> 5;
        const int cc = (c & 31) * 4;
        const size_t src = ((size_t)(b * GG + pg0 + r)) * 128 + cc;
        CP_ASYNC16(smaddr + (uint32_t)(SM_K + buf * KVBUF + r * 132 + cc) * 4u,
                   g_K + src);
        CP_ASYNC16(smaddr + (uint32_t)(SM_V + buf * KVBUF + r * 132 + cc) * 4u,
                   g_V + src);
    }
}

__device__ __forceinline__ void mlp8(const unsigned long long* __restrict__ wtU,
                                     const unsigned long long* x2,
                                     float* y0, float* y1)
{
    unsigned long long hid[8];
#pragma unroll
    for (int j = 0; j < 8; j++) {
        unsigned long long z = wtU[64 + j];
#pragma unroll
        for (int i = 0; i < 8; i++) fma2(z, wtU[j * 8 + i], x2[i]);
        float zl, zh; unpack2(z, zl, zh);
        hid[j] = pack2(fmaxf(zl, 0.f), fmaxf(zh, 0.f));
    }
#pragma unroll
    for (int h = 0; h < 4; h++) {
        unsigned long long z = wtU[104 + h];
#pragma unroll
        for (int j = 0; j < 8; j++) fma2(z, wtU[72 + h * 8 + j], hid[j]);
        unpack2(z, y0[h], y1[h]);
    }
}

__global__ __launch_bounds__(NT)
void attn_kernel(const float* __restrict__ osa,
                 const float* __restrict__ w1,
                 const float* __restrict__ b1,
                 const float* __restrict__ w2,
                 const float* __restrict__ b2,
                 float* __restrict__ osaCopy,
                 int doCopy)
{
    extern __shared__ float sm[];
    const uint32_t smaddr = (uint32_t)__cvta_generic_to_shared(sm);

    float* SS = sm + SM_SS;
    float* cs = sm + SM_CS;
    unsigned long long* wtU = (unsigned long long*)(sm + SM_WT);

    const int tid  = threadIdx.x;
    const int warp = tid >> 5;
    const int lane = tid & 31;
    const int b    = blockIdx.y;
    const int ps   = blockIdx.z;
    const int q0   = blockIdx.x * TQ;
    const int p00  = ps * PRANGE;

    const int h    = warp & 3;          // phase S/A head
    const int q16  = (warp >> 2) * 16;  // phase S/A local q base
    const int gid  = lane >> 2;
    const int tg   = lane & 3;
    const int qm   = warp * 4;          // phase M local q base

    if (tid < 108) {
        float v;
        if (tid < 64)       v = __ldg(w1 + tid);
        else if (tid < 72)  v = __ldg(b1 + tid - 64);
        else if (tid < 104) v = __ldg(w2 + tid - 72);
        else                v = __ldg(b2 + tid - 104);
        wtU[tid] = pack2(v, v);
    }

    // ---- preload Q A-fragments (tile-invariant): rows q16+gid/+8, cols h*32+.. ----
    uint32_t Afr[4][4];
    {
        const float* gq = g_Q + (size_t)(b * GG + q0 + q16 + gid) * 128 + h * 32 + tg;
#pragma unroll
        for (int ks = 0; ks < 4; ks++) {
            Afr[ks][0] = __float_as_uint(__ldg(gq + ks * 8));
            Afr[ks][1] = __float_as_uint(__ldg(gq + ks * 8 + 8 * 128));
            Afr[ks][2] = __float_as_uint(__ldg(gq + ks * 8 + 4));
            Afr[ks][3] = __float_as_uint(__ldg(gq + ks * 8 + 4 + 8 * 128));
        }
    }

    stage_cp(smaddr, 0, b, p00, tid);
    CP_COMMIT();

    float O[4][4];                  // AV accumulators (phase A), per n-tile
    float m[4][4], lln[4][4];       // softmax state (phase M), per local q, h
#pragma unroll
    for (int i = 0; i < 4; i++)
#pragma unroll
        for (int j = 0; j < 4; j++) { O[i][j] = 0.f; m[i][j] = -1e30f; lln[i][j] = 0.f; }

    for (int pt = 0; pt < NTILE; pt++) {
        const int pg0 = p00 + pt * TP;
        const int buf = pt & 1;

        // ---- osa prefetch + pass-through copy (regs die immediately) ----
        {
#pragma unroll
            for (int q = 0; q < 4; q++) {
                const int qg = q0 + qm + q;
#pragma unroll
                for (int hh = 0; hh < 4; hh++) {
                    const size_t idx =
                        ((size_t)(hh * BB + b) * GG + qg) * GG + pg0 + 2 * lane;
                    const unsigned long long v =
                        __ldg((const unsigned long long*)(osa + idx));
                    if (doCopy)
                        *(unsigned long long*)(osaCopy + idx) = v;
                }
            }
        }

        CP_WAIT0();
        __syncthreads();

        if (pt + 1 < NTILE) {
            stage_cp(smaddr, buf ^ 1, b, pg0 + TP, tid);
            CP_COMMIT();
        }

        const float* Ks = sm + SM_K + buf * KVBUF;
        const float* Vs = sm + SM_V + buf * KVBUF;

        // ================= phase S: scores via MMA =================
        {
            const float* kb = Ks + gid * 132 + h * 32 + tg;
            float* sb = SS + h * 4224 + (q16 + gid) * 66 + 2 * tg;
#pragma unroll
            for (int nt = 0; nt < 8; nt++) {
                float d0 = 0.f, d1 = 0.f, d2 = 0.f, d3 = 0.f;
#pragma unroll
                for (int ks = 0; ks < 4; ks++) {
                    const uint32_t b0 = __float_as_uint(kb[nt * 1056 + ks * 8]);
                    const uint32_t b1v = __float_as_uint(kb[nt * 1056 + ks * 8 + 4]);
                    mma_tf32(d0, d1, d2, d3,
                             Afr[ks][0], Afr[ks][1], Afr[ks][2], Afr[ks][3], b0, b1v);
                }
                *(unsigned long long*)(sb + nt * 8)       = pack2(d0, d1);
                *(unsigned long long*)(sb + nt * 8 + 528) = pack2(d2, d3);
            }
        }
        __syncthreads();   // S visible

        // ================= phase M: MLP + online softmax =================
        {
            const float* smq = SS + qm * 66 + 2 * lane;
#pragma unroll
            for (int q = 0; q < 4; q++) {
                unsigned long long x2[8];
#pragma unroll
                for (int hh = 0; hh < 4; hh++)
                    x2[hh] = *(const unsigned long long*)(smq + q * 66 + hh * 4224);
#pragma unroll
                for (int hh = 0; hh < 4; hh++) {
                    const size_t idx =
                        ((size_t)(hh * BB + b) * GG + (q0 + qm + q)) * GG + pg0 + 2 * lane;
                    x2[4 + hh] = __ldg((const unsigned long long*)(osa + idx)); // L1 hit
                }
                float y0[4], y1[4];
                mlp8(wtU, x2, y0, y1);

                float carr[4] = {1.f, 1.f, 1.f, 1.f};
                bool need = false;
#pragma unroll
                for (int hh = 0; hh < 4; hh++)
                    need |= (fmaxf(y0[hh], y1[hh]) > m[q][hh]);
                if (__ballot_sync(0xffffffffu, need)) {
#pragma unroll
                    for (int hh = 0; hh < 4; hh++) {
                        float t = fmaxf(y0[hh], y1[hh]);
#pragma unroll
                        for (int off = 16; off; off >>= 1)
                            t = fmaxf(t, __shfl_xor_sync(0xffffffffu, t, off));
                        if (t > m[q][hh]) {
                            carr[hh] = __expf(m[q][hh] - t);
                            lln[q][hh] *= carr[hh];
                            m[q][hh] = t;
                        }
                    }
                }
#pragma unroll
                for (int hh = 0; hh < 4; hh++) {
                    const float wa = __expf(y0[hh] - m[q][hh]);
                    const float wb = __expf(y1[hh] - m[q][hh]);
                    lln[q][hh] += wa + wb;
                    *(unsigned long long*)(SS + hh * 4224 + (qm + q) * 66 + 2 * lane) =
                        pack2(__uint_as_float(to_tf32(wa)), __uint_as_float(to_tf32(wb)));
                    if (lane == 0) cs[(qm + q) * 4 + hh] = carr[hh];
                }
            }
        }
        __syncthreads();   // P + corr visible

        // ================= phase A: AV via MMA =================
        {
            const float c0 = cs[(q16 + gid) * 4 + h];
            const float c1 = cs[(q16 + gid + 8) * 4 + h];
#pragma unroll
            for (int nt = 0; nt < 4; nt++) {
                O[nt][0] *= c0; O[nt][1] *= c0;
                O[nt][2] *= c1; O[nt][3] *= c1;
            }
            uint32_t Pa[8][4];
            const float* pb = SS + h * 4224 + (q16 + gid) * 66 + tg;
#pragma unroll
            for (int ks = 0; ks < 8; ks++) {
                Pa[ks][0] = __float_as_uint(pb[ks * 8]);
                Pa[ks][1] = __float_as_uint(pb[ks * 8 + 528]);
                Pa[ks][2] = __float_as_uint(pb[ks * 8 + 4]);
                Pa[ks][3] = __float_as_uint(pb[ks * 8 + 532]);
            }
            const float* vb = Vs + tg * 132 + h * 32 + gid;
#pragma unroll
            for (int nt = 0; nt < 4; nt++) {
#pragma unroll
                for (int ks = 0; ks < 8; ks++) {
                    const uint32_t b0 = __float_as_uint(vb[ks * 1056 + nt * 8]);
                    const uint32_t b1v = __float_as_uint(vb[ks * 1056 + 528 + nt * 8]);
                    mma_tf32(O[nt][0], O[nt][1], O[nt][2], O[nt][3],
                             Pa[ks][0], Pa[ks][1], Pa[ks][2], Pa[ks][3], b0, b1v);
                }
            }
        }
    }

    // ---- epilogue: softmax state (phase-M role) ----
#pragma unroll
    for (int q = 0; q < 4; q++) {
        const int row = b * GG + q0 + qm + q;
#pragma unroll
        for (int hh = 0; hh < 4; hh++) {
            float ls = lln[q][hh];
#pragma unroll
            for (int off = 16; off; off >>= 1)
                ls += __shfl_xor_sync(0xffffffffu, ls, off);
            if (lane == 0) {
                g_pm[ps][row * 4 + hh] = m[q][hh];
                g_pl[ps][row * 4 + hh] = ls;
            }
        }
    }
    // ---- epilogue: O fragments (phase-A role) ----
    {
        const int rowA = b * GG + q0 + q16 + gid;
        const int rowB = rowA + 8;
#pragma unroll
        for (int nt = 0; nt < 4; nt++) {
            const int col = h * 32 + nt * 8 + 2 * tg;
            *(unsigned long long*)(&g_pacc[ps][(size_t)rowA * 128 + col]) =
                pack2(O[nt][0], O[nt][1]);
            *(unsigned long long*)(&g_pacc[ps][(size_t)rowB * 128 + col]) =
                pack2(O[nt][2], O[nt][3]);
        }
    }
}

// =============================================================================
// K2: combine p-split partials + output projection.
// =============================================================================
__global__ __launch_bounds__(128)
void outproj_kernel(const float* __restrict__ Wout,
                    float* __restrict__ out)
{
    __shared__ float hs[8 * 128];
    __shared__ float fc[8][4][PSPLIT];
    const int tid  = threadIdx.x;
    const int row0 = blockIdx.x * 8;

    if (tid < 32) {
        const int r = tid >> 2, h = tid & 3;
        const int idx = (row0 + r) * 4 + h;
        float mm[PSPLIT], ll[PSPLIT];
        float M = -1e30f;
#pragma unroll
        for (int p = 0; p < PSPLIT; p++) {
            mm[p] = g_pm[p][idx];
            ll[p] = g_pl[p][idx];
            M = fmaxf(M, mm[p]);
        }
        float L = 0.f, e[PSPLIT];
#pragma unroll
        for (int p = 0; p < PSPLIT; p++) {
            e[p] = __expf(mm[p] - M);
            L += ll[p] * e[p];
        }
#pragma unroll
        for (int p = 0; p < PSPLIT; p++) fc[r][h][p] = e[p] / L;
    }
    __syncthreads();

    for (int i = tid; i < 8 * 128; i += 128) {
        const int r = i >> 7, c = i & 127, h = c >> 5;
        float v = 0.f;
#pragma unroll
        for (int p = 0; p < PSPLIT; p++)
            v += g_pacc[p][(size_t)(row0 + r) * 128 + c] * fc[r][h][p];
        hs[i] = v;
    }
    __syncthreads();

    float a[8];
#pragma unroll
    for (int r = 0; r < 8; r++) a[r] = 0.f;

    for (int t = 0; t < 128; t += 4) {
        float w[4];
#pragma unroll
        for (int u = 0; u < 4; u++) w[u] = __ldg(Wout + (t + u) * 128 + tid);
#pragma unroll
        for (int u = 0; u < 4; u++)
#pragma unroll
            for (int r = 0; r < 8; r++) a[r] += hs[r * 128 + t + u] * w[u];
    }
#pragma unroll
    for (int r = 0; r < 8; r++)
        out[(size_t)(row0 + r) * 128 + tid] = a[r];
}

// =============================================================================
extern "C" void kernel_launch(void* const* d_in, const int* in_sizes, int n_in,
                              void* d_out, int out_size)
{
    const float* hin  = (const float*)d_in[0];
    const float* osa  = (const float*)d_in[1];
    const float* Wq   = (const float*)d_in[2];
    const float* Wk   = (const float*)d_in[3];
    const float* Wv   = (const float*)d_in[4];
    const float* Wout = (const float*)d_in[5];
    const float* w1   = (const float*)d_in[6];
    const float* b1   = (const float*)d_in[7];
    const float* w2   = (const float*)d_in[8];
    const float* b2   = (const float*)d_in[9];
    (void)in_sizes; (void)n_in;

    float* out = (float*)d_out;

    const int OUT_ELEMS = BB * GG * EE;
    const long long OSA_ELEMS = (long long)HH * BB * GG * GG;
    const int doCopy = ((long long)out_size >= OUT_ELEMS + OSA_ELEMS) ? 1 : 0;
    float* osaCopy = doCopy ? (out + OUT_ELEMS) : out;

    cudaFuncSetAttribute(attn_kernel,
                         cudaFuncAttributeMaxDynamicSharedMemorySize, SMEM_BYTES);

    qkv_kernel<<<BB * GG / 8, 256>>>(hin, Wq, Wk, Wv);
    attn_kernel<<<dim3(GG / TQ, BB, PSPLIT), NT, SMEM_BYTES>>>(
        osa, w1, b1, w2, b2, osaCopy, doCopy);
    outproj_kernel<<<BB * GG / 8, 128>>>(Wout, out);
}

// round 17
// speedup vs baseline: 1.1074x; 1.1074x over previous
#include <cuda_runtime.h>
#include <cuda_bf16.h>
#include <cstdint>

#define BB 2
#define GG 2048
#define HH 4
#define EE 128

#define TQ 64      // q rows per block (16 warps)
#define TP 64      // p columns per tile
#define PSPLIT 2
#define PRANGE (GG / PSPLIT)      // 1024
#define NTILE (PRANGE / TP)       // 16
#define NT 512     // 16 warps

// ---------------- device scratch ----------------
__device__ float g_Q[BB * GG * 128];     // tf32-rounded
__device__ float g_K[BB * GG * 128];     // tf32-rounded
__device__ float g_V[BB * GG * 128];     // tf32-rounded, natural layout
__device__ float g_pacc[PSPLIT][BB * GG * 128];
__device__ float g_pm[PSPLIT][BB * GG * 4];
__device__ float g_pl[PSPLIT][BB * GG * 4];

// ---------------- helpers ----------------
__device__ __forceinline__ unsigned long long pack2(float a, float b) {
    unsigned long long r;
    asm("mov.b64 %0, {%1, %2};" : "=l"(r) : "f"(a), "f"(b));
    return r;
}
__device__ __forceinline__ void unpack2(unsigned long long v, float& a, float& b) {
    asm("mov.b64 {%0, %1}, %2;" : "=f"(a), "=f"(b) : "l"(v));
}
__device__ __forceinline__ void fma2(unsigned long long& d,
                                     unsigned long long a, unsigned long long b) {
    asm("fma.rn.f32x2 %0, %1, %2, %0;" : "+l"(d) : "l"(a), "l"(b));
}
__device__ __forceinline__ uint32_t to_tf32(float f) {
    uint32_t r;
    asm("cvt.rna.tf32.f32 %0, %1;" : "=r"(r) : "f"(f));
    return r;
}
__device__ __forceinline__ void mma_tf32(float& d0, float& d1, float& d2, float& d3,
                                         uint32_t a0, uint32_t a1, uint32_t a2, uint32_t a3,
                                         uint32_t b0, uint32_t b1) {
    asm volatile("mma.sync.aligned.m16n8k8.row.col.f32.tf32.tf32.f32 "
                 "{%0,%1,%2,%3}, {%4,%5,%6,%7}, {%8,%9}, {%0,%1,%2,%3};"
                 : "+f"(d0), "+f"(d1), "+f"(d2), "+f"(d3)
                 : "r"(a0), "r"(a1), "r"(a2), "r"(a3), "r"(b0), "r"(b1));
}

#define CP_ASYNC16(dst, src) \
    asm volatile("cp.async.cg.shared.global [%0], [%1], 16;" :: "r"(dst), "l"(src))
#define CP_COMMIT() asm volatile("cp.async.commit_group;" ::: "memory")
#define CP_WAIT0()  asm volatile("cp.async.wait_group 0;" ::: "memory")

// =============================================================================
// K0: fused QKV projection; outputs tf32-rounded; V natural layout.
// d-loop batched x8: 24 weight LDGs in flight per step (latency hiding).
// =============================================================================
__global__ __launch_bounds__(256)
void qkv_kernel(const float* __restrict__ hin,
                const float* __restrict__ Wq,
                const float* __restrict__ Wk,
                const float* __restrict__ Wv)
{
    __shared__ float hs[8 * 128];
    const int tid  = threadIdx.x;
    const int row0 = blockIdx.x * 8;

    for (int i = tid; i < 8 * 128; i += 256)
        hs[i] = hin[(size_t)row0 * 128 + i];
    __syncthreads();

    const int sub   = tid >> 7;
    const int col   = tid & 127;
    const int rbase = sub * 4;

    float aq[4], ak[4], av[4];
#pragma unroll
    for (int r = 0; r < 4; r++) { aq[r] = 0.f; ak[r] = 0.f; av[r] = 0.f; }

    const int hh = col >> 5, k = col & 31;
    const float* wqp = Wq + hh * 128 * 32 + k;
    const float* wkp = Wk + hh * 128 * 32 + k;
    const float* wvp = Wv + hh * 128 * 32 + k;

    for (int d = 0; d < 128; d += 8) {
        float wq[8], wk8[8], wv[8];
#pragma unroll
        for (int u = 0; u < 8; u++) {
            wq[u]  = __ldg(wqp + (d + u) * 32);
            wk8[u] = __ldg(wkp + (d + u) * 32);
            wv[u]  = __ldg(wvp + (d + u) * 32);
        }
#pragma unroll
        for (int u = 0; u < 8; u++) {
#pragma unroll
            for (int r = 0; r < 4; r++) {
                const float hv = hs[(rbase + r) * 128 + d + u];
                aq[r] += hv * wq[u];
                ak[r] += hv * wk8[u];
                av[r] += hv * wv[u];
            }
        }
    }

    const int growbase = row0 + rbase;
#pragma unroll
    for (int r = 0; r < 4; r++) {
        const size_t o = (size_t)(growbase + r) * 128 + col;
        g_Q[o] = __uint_as_float(to_tf32(aq[r]));
        g_K[o] = __uint_as_float(to_tf32(ak[r]));
        g_V[o] = __uint_as_float(to_tf32(av[r]));
    }
}

// =============================================================================
// K1: tf32 warp-MMA scores + AV, SIMT MLP/softmax between, 3-phase per tile.
// osa read ONCE per tile into registers (issued during phase S), copy stored
// from the same registers in phase M (streaming .cs both ways).
// grid = (32, 2, 2) = 128 blocks, 512 thr = 16 warps, smem 204,640 B.
// =============================================================================
#define SM_K  0                    /* 2 x 64 x 132 = 16896 */
#define SM_V  16896                /* 2 x 64 x 132 = 16896 */
#define SM_SS 33792                /* 4h x 64q x 66 = 16896 (S, then P) */
#define SM_CS 50688                /* 64q x 4h = 256 */
#define SM_WT 50944                /* 108 ull = 216 */
#define SMEM_FLOATS 51160
#define SMEM_BYTES (SMEM_FLOATS * 4)
#define KVBUF 8448                 /* floats per buffer */

__device__ __forceinline__ void stage_cp(uint32_t smaddr, int buf, int b,
                                         int pg0, int tid)
{
#pragma unroll
    for (int j = 0; j < 4; j++) {
        const int c  = tid + j * 512;
        const int r  = c >> 5;
        const int cc = (c & 31) * 4;
        const size_t src = ((size_t)(b * GG + pg0 + r)) * 128 + cc;
        CP_ASYNC16(smaddr + (uint32_t)(SM_K + buf * KVBUF + r * 132 + cc) * 4u,
                   g_K + src);
        CP_ASYNC16(smaddr + (uint32_t)(SM_V + buf * KVBUF + r * 132 + cc) * 4u,
                   g_V + src);
    }
}

__device__ __forceinline__ void mlp8(const unsigned long long* __restrict__ wtU,
                                     const unsigned long long* x2,
                                     float* y0, float* y1)
{
    unsigned long long hid[8];
#pragma unroll
    for (int j = 0; j < 8; j++) {
        unsigned long long z = wtU[64 + j];
#pragma unroll
        for (int i = 0; i < 8; i++) fma2(z, wtU[j * 8 + i], x2[i]);
        float zl, zh; unpack2(z, zl, zh);
        hid[j] = pack2(fmaxf(zl, 0.f), fmaxf(zh, 0.f));
    }
#pragma unroll
    for (int h = 0; h < 4; h++) {
        unsigned long long z = wtU[104 + h];
#pragma unroll
        for (int j = 0; j < 8; j++) fma2(z, wtU[72 + h * 8 + j], hid[j]);
        unpack2(z, y0[h], y1[h]);
    }
}

__global__ __launch_bounds__(NT)
void attn_kernel(const float* __restrict__ osa,
                 const float* __restrict__ w1,
                 const float* __restrict__ b1,
                 const float* __restrict__ w2,
                 const float* __restrict__ b2,
                 float* __restrict__ osaCopy,
                 int doCopy)
{
    extern __shared__ float sm[];
    const uint32_t smaddr = (uint32_t)__cvta_generic_to_shared(sm);

    float* SS = sm + SM_SS;
    float* cs = sm + SM_CS;
    unsigned long long* wtU = (unsigned long long*)(sm + SM_WT);

    const int tid  = threadIdx.x;
    const int warp = tid >> 5;
    const int lane = tid & 31;
    const int b    = blockIdx.y;
    const int ps   = blockIdx.z;
    const int q0   = blockIdx.x * TQ;
    const int p00  = ps * PRANGE;

    const int h    = warp & 3;          // phase S/A head
    const int q16  = (warp >> 2) * 16;  // phase S/A local q base
    const int gid  = lane >> 2;
    const int tg   = lane & 3;
    const int qm   = warp * 4;          // phase M local q base

    if (tid < 108) {
        float v;
        if (tid < 64)       v = __ldg(w1 + tid);
        else if (tid < 72)  v = __ldg(b1 + tid - 64);
        else if (tid < 104) v = __ldg(w2 + tid - 72);
        else                v = __ldg(b2 + tid - 104);
        wtU[tid] = pack2(v, v);
    }

    // ---- preload Q A-fragments (tile-invariant) ----
    uint32_t Afr[4][4];
    {
        const float* gq = g_Q + (size_t)(b * GG + q0 + q16 + gid) * 128 + h * 32 + tg;
#pragma unroll
        for (int ks = 0; ks < 4; ks++) {
            Afr[ks][0] = __float_as_uint(__ldg(gq + ks * 8));
            Afr[ks][1] = __float_as_uint(__ldg(gq + ks * 8 + 8 * 128));
            Afr[ks][2] = __float_as_uint(__ldg(gq + ks * 8 + 4));
            Afr[ks][3] = __float_as_uint(__ldg(gq + ks * 8 + 4 + 8 * 128));
        }
    }

    stage_cp(smaddr, 0, b, p00, tid);
    CP_COMMIT();

    float O[4][4];                  // AV accumulators (phase A)
    float m[4][4], lln[4][4];       // softmax state (phase M)
#pragma unroll
    for (int i = 0; i < 4; i++)
#pragma unroll
        for (int j = 0; j < 4; j++) { O[i][j] = 0.f; m[i][j] = -1e30f; lln[i][j] = 0.f; }

    for (int pt = 0; pt < NTILE; pt++) {
        const int pg0 = p00 + pt * TP;
        const int buf = pt & 1;

        CP_WAIT0();
        __syncthreads();

        if (pt + 1 < NTILE) {
            stage_cp(smaddr, buf ^ 1, b, pg0 + TP, tid);
            CP_COMMIT();
        }

        // ---- osa loads for phase-M rows: issued here, in flight over phase S ----
        unsigned long long o2[4][4];
#pragma unroll
        for (int q = 0; q < 4; q++) {
            const int qg = q0 + qm + q;
#pragma unroll
            for (int hh = 0; hh < 4; hh++) {
                const size_t idx =
                    ((size_t)(hh * BB + b) * GG + qg) * GG + pg0 + 2 * lane;
                o2[q][hh] = __ldcs((const unsigned long long*)(osa + idx));
            }
        }

        const float* Ks = sm + SM_K + buf * KVBUF;
        const float* Vs = sm + SM_V + buf * KVBUF;

        // ================= phase S: scores via MMA =================
        {
            const float* kb = Ks + gid * 132 + h * 32 + tg;
            float* sb = SS + h * 4224 + (q16 + gid) * 66 + 2 * tg;
#pragma unroll
            for (int nt = 0; nt < 8; nt++) {
                float d0 = 0.f, d1 = 0.f, d2 = 0.f, d3 = 0.f;
#pragma unroll
                for (int ks = 0; ks < 4; ks++) {
                    const uint32_t b0 = __float_as_uint(kb[nt * 1056 + ks * 8]);
                    const uint32_t b1v = __float_as_uint(kb[nt * 1056 + ks * 8 + 4]);
                    mma_tf32(d0, d1, d2, d3,
                             Afr[ks][0], Afr[ks][1], Afr[ks][2], Afr[ks][3], b0, b1v);
                }
                *(unsigned long long*)(sb + nt * 8)       = pack2(d0, d1);
                *(unsigned long long*)(sb + nt * 8 + 528) = pack2(d2, d3);
            }
        }
        __syncthreads();   // S visible

        // ================= phase M: MLP + online softmax =================
        {
            // pass-through copy from registers (streaming stores)
            if (doCopy) {
#pragma unroll
                for (int q = 0; q < 4; q++) {
                    const int qg = q0 + qm + q;
#pragma unroll
                    for (int hh = 0; hh < 4; hh++) {
                        const size_t idx =
                            ((size_t)(hh * BB + b) * GG + qg) * GG + pg0 + 2 * lane;
                        __stcs((unsigned long long*)(osaCopy + idx), o2[q][hh]);
                    }
                }
            }

            const float* smq = SS + qm * 66 + 2 * lane;
#pragma unroll
            for (int q = 0; q < 4; q++) {
                unsigned long long x2[8];
#pragma unroll
                for (int hh = 0; hh < 4; hh++)
                    x2[hh] = *(const unsigned long long*)(smq + q * 66 + hh * 4224);
#pragma unroll
                for (int hh = 0; hh < 4; hh++)
                    x2[4 + hh] = o2[q][hh];

                float y0[4], y1[4];
                mlp8(wtU, x2, y0, y1);

                float carr[4] = {1.f, 1.f, 1.f, 1.f};
                bool need = false;
#pragma unroll
                for (int hh = 0; hh < 4; hh++)
                    need |= (fmaxf(y0[hh], y1[hh]) > m[q][hh]);
                if (__ballot_sync(0xffffffffu, need)) {
#pragma unroll
                    for (int hh = 0; hh < 4; hh++) {
                        float t = fmaxf(y0[hh], y1[hh]);
#pragma unroll
                        for (int off = 16; off; off >>= 1)
                            t = fmaxf(t, __shfl_xor_sync(0xffffffffu, t, off));
                        if (t > m[q][hh]) {
                            carr[hh] = __expf(m[q][hh] - t);
                            lln[q][hh] *= carr[hh];
                            m[q][hh] = t;
                        }
                    }
                }
#pragma unroll
                for (int hh = 0; hh < 4; hh++) {
                    const float wa = __expf(y0[hh] - m[q][hh]);
                    const float wb = __expf(y1[hh] - m[q][hh]);
                    lln[q][hh] += wa + wb;
                    *(unsigned long long*)(SS + hh * 4224 + (qm + q) * 66 + 2 * lane) =
                        pack2(__uint_as_float(to_tf32(wa)), __uint_as_float(to_tf32(wb)));
                    if (lane == 0) cs[(qm + q) * 4 + hh] = carr[hh];
                }
            }
        }
        __syncthreads();   // P + corr visible

        // ================= phase A: AV via MMA =================
        {
            const float c0 = cs[(q16 + gid) * 4 + h];
            const float c1 = cs[(q16 + gid + 8) * 4 + h];
#pragma unroll
            for (int nt = 0; nt < 4; nt++) {
                O[nt][0] *= c0; O[nt][1] *= c0;
                O[nt][2] *= c1; O[nt][3] *= c1;
            }
            uint32_t Pa[8][4];
            const float* pb = SS + h * 4224 + (q16 + gid) * 66 + tg;
#pragma unroll
            for (int ks = 0; ks < 8; ks++) {
                Pa[ks][0] = __float_as_uint(pb[ks * 8]);
                Pa[ks][1] = __float_as_uint(pb[ks * 8 + 528]);
                Pa[ks][2] = __float_as_uint(pb[ks * 8 + 4]);
                Pa[ks][3] = __float_as_uint(pb[ks * 8 + 532]);
            }
            const float* vb = Vs + tg * 132 + h * 32 + gid;
#pragma unroll
            for (int nt = 0; nt < 4; nt++) {
#pragma unroll
                for (int ks = 0; ks < 8; ks++) {
                    const uint32_t b0 = __float_as_uint(vb[ks * 1056 + nt * 8]);
                    const uint32_t b1v = __float_as_uint(vb[ks * 1056 + 528 + nt * 8]);
                    mma_tf32(O[nt][0], O[nt][1], O[nt][2], O[nt][3],
                             Pa[ks][0], Pa[ks][1], Pa[ks][2], Pa[ks][3], b0, b1v);
                }
            }
        }
    }

    // ---- epilogue: softmax state (phase-M role) ----
#pragma unroll
    for (int q = 0; q < 4; q++) {
        const int row = b * GG + q0 + qm + q;
#pragma unroll
        for (int hh = 0; hh < 4; hh++) {
            float ls = lln[q][hh];
#pragma unroll
            for (int off = 16; off; off >>= 1)
                ls += __shfl_xor_sync(0xffffffffu, ls, off);
            if (lane == 0) {
                g_pm[ps][row * 4 + hh] = m[q][hh];
                g_pl[ps][row * 4 + hh] = ls;
            }
        }
    }
    // ---- epilogue: O fragments (phase-A role) ----
    {
        const int rowA = b * GG + q0 + q16 + gid;
        const int rowB = rowA + 8;
#pragma unroll
        for (int nt = 0; nt < 4; nt++) {
            const int col = h * 32 + nt * 8 + 2 * tg;
            *(unsigned long long*)(&g_pacc[ps][(size_t)rowA * 128 + col]) =
                pack2(O[nt][0], O[nt][1]);
            *(unsigned long long*)(&g_pacc[ps][(size_t)rowB * 128 + col]) =
                pack2(O[nt][2], O[nt][3]);
        }
    }
}

// =============================================================================
// K2: combine p-split partials + output projection.
// =============================================================================
__global__ __launch_bounds__(128)
void outproj_kernel(const float* __restrict__ Wout,
                    float* __restrict__ out)
{
    __shared__ float hs[8 * 128];
    __shared__ float fc[8][4][PSPLIT];
    const int tid  = threadIdx.x;
    const int row0 = blockIdx.x * 8;

    if (tid < 32) {
        const int r = tid >> 2, h = tid & 3;
        const int idx = (row0 + r) * 4 + h;
        float mm[PSPLIT], ll[PSPLIT];
        float M = -1e30f;
#pragma unroll
        for (int p = 0; p < PSPLIT; p++) {
            mm[p] = g_pm[p][idx];
            ll[p] = g_pl[p][idx];
            M = fmaxf(M, mm[p]);
        }
        float L = 0.f, e[PSPLIT];
#pragma unroll
        for (int p = 0; p < PSPLIT; p++) {
            e[p] = __expf(mm[p] - M);
            L += ll[p] * e[p];
        }
#pragma unroll
        for (int p = 0; p < PSPLIT; p++) fc[r][h][p] = e[p] / L;
    }
    __syncthreads();

    for (int i = tid; i < 8 * 128; i += 128) {
        const int r = i >> 7, c = i & 127, h = c >> 5;
        float v = 0.f;
#pragma unroll
        for (int p = 0; p < PSPLIT; p++)
            v += g_pacc[p][(size_t)(row0 + r) * 128 + c] * fc[r][h][p];
        hs[i] = v;
    }
    __syncthreads();

    float a[8];
#pragma unroll
    for (int r = 0; r < 8; r++) a[r] = 0.f;

    for (int t = 0; t < 128; t += 4) {
        float w[4];
#pragma unroll
        for (int u = 0; u < 4; u++) w[u] = __ldg(Wout + (t + u) * 128 + tid);
#pragma unroll
        for (int u = 0; u < 4; u++)
#pragma unroll
            for (int r = 0; r < 8; r++) a[r] += hs[r * 128 + t + u] * w[u];
    }
#pragma unroll
    for (int r = 0; r < 8; r++)
        out[(size_t)(row0 + r) * 128 + tid] = a[r];
}

// =============================================================================
extern "C" void kernel_launch(void* const* d_in, const int* in_sizes, int n_in,
                              void* d_out, int out_size)
{
    const float* hin  = (const float*)d_in[0];
    const float* osa  = (const float*)d_in[1];
    const float* Wq   = (const float*)d_in[2];
    const float* Wk   = (const float*)d_in[3];
    const float* Wv   = (const float*)d_in[4];
    const float* Wout = (const float*)d_in[5];
    const float* w1   = (const float*)d_in[6];
    const float* b1   = (const float*)d_in[7];
    const float* w2   = (const float*)d_in[8];
    const float* b2   = (const float*)d_in[9];
    (void)in_sizes; (void)n_in;

    float* out = (float*)d_out;

    const int OUT_ELEMS = BB * GG * EE;
    const long long OSA_ELEMS = (long long)HH * BB * GG * GG;
    const int doCopy = ((long long)out_size >= OUT_ELEMS + OSA_ELEMS) ? 1 : 0;
    float* osaCopy = doCopy ? (out + OUT_ELEMS) : out;

    cudaFuncSetAttribute(attn_kernel,
                         cudaFuncAttributeMaxDynamicSharedMemorySize, SMEM_BYTES);

    qkv_kernel<<<BB * GG / 8, 256>>>(hin, Wq, Wk, Wv);
    attn_kernel<<<dim3(GG / TQ, BB, PSPLIT), NT, SMEM_BYTES>>>(
        osa, w1, b1, w2, b2, osaCopy, doCopy);
    outproj_kernel<<<BB * GG / 8, 128>>>(Wout, out);
}